// round 10
// baseline (speedup 1.0000x reference)
#include <cuda_runtime.h>

#define D_MODEL 4096
#define D_INNER 8192
#define D_STATE 16
#define DT_RANK 8
#define XP_DIM  (DT_RANK + 2 * D_STATE)   // 40

// ---------------- scratch (device globals; no allocation allowed) ------------
__device__ float g_x_conv[D_INNER];
__device__ float g_z[D_INNER];
__device__ float g_xp[XP_DIM];
__device__ float g_y[D_INNER];
__device__ float g_h_scratch[D_INNER * D_STATE];

// ---------------- helpers ----------------------------------------------------
__device__ __forceinline__ float warp_reduce(float v) {
#pragma unroll
    for (int o = 16; o; o >>= 1) v += __shfl_xor_sync(0xffffffffu, v, o);
    return v;
}

__device__ __forceinline__ float fma4(float4 w, float4 v, float a) {
    return fmaf(w.x, v.x, fmaf(w.y, v.y, fmaf(w.z, v.z, fmaf(w.w, v.w, a))));
}

__device__ __forceinline__ float sigmoidf_(float v) { return 1.f / (1.f + expf(-v)); }

// ---------------- kernel 1: xz = W_in @ x, fused conv+silu epilogue ----------
// 16384 rows x 4096 cols. One warp handles TWO rows of the same channel:
// row ch (x-branch) and row ch+8192 (z). 8 channels per 256-thread block.
// Grid = D_INNER/8 = 1024 blocks. 12 independent LDG.128 per unroll body.
__global__ void __launch_bounds__(256) k_gemv_in(
    const float* __restrict__ W,        // (16384, 4096)
    const float* __restrict__ x,        // (4096,)
    const float* __restrict__ cb,       // conv_buffer (8192, 3)
    const float* __restrict__ cw,       // conv_w (8192, 4)
    const float* __restrict__ conv_b)   // (8192,)
{
    const int warp = threadIdx.x >> 5, lane = threadIdx.x & 31;
    const int ch = blockIdx.x * 8 + warp;          // channel 0..8191

    const float4* __restrict__ Wx = (const float4*)(W + (size_t)ch * D_MODEL);
    const float4* __restrict__ Wz = (const float4*)(W + (size_t)(ch + D_INNER) * D_MODEL);
    const float4* __restrict__ xv = (const float4*)x;

    float x0 = 0.f, x1 = 0.f, x2 = 0.f, x3 = 0.f;
    float z0 = 0.f, z1 = 0.f, z2 = 0.f, z3 = 0.f;
#pragma unroll
    for (int k = 0; k < 32; k += 4) {               // 1024 float4 per row / 32 lanes
        const int b = k * 32 + lane;
        const float4 v0 = __ldg(&xv[b]);
        const float4 v1 = __ldg(&xv[b + 32]);
        const float4 v2 = __ldg(&xv[b + 64]);
        const float4 v3 = __ldg(&xv[b + 96]);
        const float4 a0 = Wx[b],      a1 = Wx[b + 32],
                     a2 = Wx[b + 64], a3 = Wx[b + 96];
        const float4 c0 = Wz[b],      c1 = Wz[b + 32],
                     c2 = Wz[b + 64], c3 = Wz[b + 96];
        x0 = fma4(a0, v0, x0);  x1 = fma4(a1, v1, x1);
        x2 = fma4(a2, v2, x2);  x3 = fma4(a3, v3, x3);
        z0 = fma4(c0, v0, z0);  z1 = fma4(c1, v1, z1);
        z2 = fma4(c2, v2, z2);  z3 = fma4(c3, v3, z3);
    }
    const float accx = warp_reduce((x0 + x1) + (x2 + x3));
    const float accz = warp_reduce((z0 + z1) + (z2 + z3));

    if (lane == 0) {
        // conv_in = [cb[:,1], cb[:,2], v, v] ; weights [w0,w1,w2,w3]
        const float c1 = cb[ch * 3 + 1];
        const float c2 = cb[ch * 3 + 2];
        const float4 w4 = *(const float4*)(cw + ch * 4);
        const float s = fmaf(c1, w4.x, fmaf(c2, w4.y, fmaf(accx, w4.z + w4.w, conv_b[ch])));
        g_x_conv[ch] = s * sigmoidf_(s);   // silu
        g_z[ch] = accz;
    }
}

// ---------------- kernel 2: xp = W_xp @ x_conv  (40 x 8192) ------------------
__global__ void __launch_bounds__(256) k_xp(const float* __restrict__ Wxp)
{
    const int row = blockIdx.x;                     // 0..39
    const float4* __restrict__ Wr = (const float4*)(Wxp + (size_t)row * D_INNER);
    const float4* __restrict__ xc = (const float4*)g_x_conv;

    float acc = 0.f;
    for (int idx = threadIdx.x; idx < D_INNER / 4; idx += 256) {
        acc = fma4(Wr[idx], xc[idx], acc);
    }
    __shared__ float sred[8];
    acc = warp_reduce(acc);
    if ((threadIdx.x & 31) == 0) sred[threadIdx.x >> 5] = acc;
    __syncthreads();
    if (threadIdx.x < 32) {
        float v = (threadIdx.x < 8) ? sred[threadIdx.x] : 0.f;
        v = warp_reduce(v);
        if (threadIdx.x == 0) g_xp[row] = v;
    }
}

// ---------------- kernel 3: dt/softplus + SSM state update + gate ------------
// One thread per channel (8192). Writes new_h and g_y.
__global__ void __launch_bounds__(256) k_state(
    const float* __restrict__ Wdt,      // (8192, 8)
    const float* __restrict__ bdt,      // (8192,)
    const float* __restrict__ Alog,     // (8192, 16)
    const float* __restrict__ h,        // ssm_state (8192, 16)
    const float* __restrict__ Dp,       // (8192,)
    float* __restrict__ newh)           // (8192, 16) or nullptr
{
    const int i = blockIdx.x * 256 + threadIdx.x;

    __shared__ float sxp[XP_DIM];
    if (threadIdx.x < XP_DIM) sxp[threadIdx.x] = g_xp[threadIdx.x];
    __syncthreads();

    // dt = softplus(W_dt[i,:] . xp[:8] + b_dt[i])
    const float4* wd = (const float4*)(Wdt + (size_t)i * DT_RANK);
    const float4 w0 = wd[0], w1 = wd[1];
    float dtin = bdt[i];
    dtin += w0.x * sxp[0] + w0.y * sxp[1] + w0.z * sxp[2] + w0.w * sxp[3]
          + w1.x * sxp[4] + w1.y * sxp[5] + w1.z * sxp[6] + w1.w * sxp[7];
    const float dt = (dtin > 20.f) ? dtin : log1pf(expf(dtin));

    const float xc = g_x_conv[i];
    const float* Ar = Alog + (size_t)i * D_STATE;
    const float* hr = h    + (size_t)i * D_STATE;
    float* nr = (newh ? newh : g_h_scratch) + (size_t)i * D_STATE;

    float acc = 0.f;
#pragma unroll
    for (int s = 0; s < D_STATE; s++) {
        const float abar = expf(-dt * expf(Ar[s]));               // exp(dt * -exp(A_log))
        const float nh = fmaf(abar, hr[s], dt * sxp[DT_RANK + s] * xc);
        nr[s] = nh;
        acc = fmaf(nh, sxp[DT_RANK + D_STATE + s], acc);
    }
    const float y = acc + Dp[i] * xc;
    const float z = g_z[i];
    g_y[i] = y * (z * sigmoidf_(z));
}

// ---------------- kernel 4: out = W_out @ y  (4096 x 8192) -------------------
// One warp handles TWO rows (r, r+2048) sharing one y-load stream.
// Grid = 2048 warps / 8 per block = 256 blocks.
__global__ void __launch_bounds__(256) k_gemv_out(
    const float* __restrict__ W, float* __restrict__ out)
{
    const int warp = threadIdx.x >> 5, lane = threadIdx.x & 31;
    const int r = blockIdx.x * 8 + warp;            // 0..2047
    const int ROWS_HALF = D_MODEL / 2;              // 2048

    const float4* __restrict__ W0 = (const float4*)(W + (size_t)r * D_INNER);
    const float4* __restrict__ W1 = (const float4*)(W + (size_t)(r + ROWS_HALF) * D_INNER);
    const float4* __restrict__ yv = (const float4*)g_y;

    float p0 = 0.f, p1 = 0.f, p2 = 0.f, p3 = 0.f;
    float q0 = 0.f, q1 = 0.f, q2 = 0.f, q3 = 0.f;
#pragma unroll
    for (int k = 0; k < 64; k += 4) {               // 2048 float4 per row / 32 lanes
        const int b = k * 32 + lane;
        const float4 v0 = __ldg(&yv[b]);
        const float4 v1 = __ldg(&yv[b + 32]);
        const float4 v2 = __ldg(&yv[b + 64]);
        const float4 v3 = __ldg(&yv[b + 96]);
        const float4 a0 = W0[b],      a1 = W0[b + 32],
                     a2 = W0[b + 64], a3 = W0[b + 96];
        const float4 c0 = W1[b],      c1 = W1[b + 32],
                     c2 = W1[b + 64], c3 = W1[b + 96];
        p0 = fma4(a0, v0, p0);  p1 = fma4(a1, v1, p1);
        p2 = fma4(a2, v2, p2);  p3 = fma4(a3, v3, p3);
        q0 = fma4(c0, v0, q0);  q1 = fma4(c1, v1, q1);
        q2 = fma4(c2, v2, q2);  q3 = fma4(c3, v3, q3);
    }
    const float acc0 = warp_reduce((p0 + p1) + (p2 + p3));
    const float acc1 = warp_reduce((q0 + q1) + (q2 + q3));
    if (lane == 0) {
        out[r] = acc0;
        out[r + ROWS_HALF] = acc1;
    }
}

// ---------------- launch ------------------------------------------------------
extern "C" void kernel_launch(void* const* d_in, const int* in_sizes, int n_in,
                              void* d_out, int out_size)
{
    const float* x       = (const float*)d_in[0];
    const float* h       = (const float*)d_in[1];   // ssm_state
    const float* cb      = (const float*)d_in[2];   // conv_buffer
    const float* W_in    = (const float*)d_in[3];
    const float* conv_w  = (const float*)d_in[4];
    const float* conv_b  = (const float*)d_in[5];
    const float* W_xp    = (const float*)d_in[6];
    const float* W_dt    = (const float*)d_in[7];
    const float* b_dt    = (const float*)d_in[8];
    const float* A_log   = (const float*)d_in[9];
    const float* D_param = (const float*)d_in[10];
    const float* W_out   = (const float*)d_in[11];

    float* out = (float*)d_out;
    // tuple output (out, new_h) concatenated: [4096][8192*16]
    float* newh = (out_size >= D_MODEL + D_INNER * D_STATE) ? (out + D_MODEL) : nullptr;

    k_gemv_in <<<D_INNER / 8, 256>>>(W_in, x, cb, conv_w, conv_b);
    k_xp      <<<XP_DIM, 256>>>(W_xp);
    k_state   <<<D_INNER / 256, 256>>>(W_dt, b_dt, A_log, h, D_param, newh);
    k_gemv_out<<<D_MODEL / 16, 256>>>(W_out, out);   // 256 blocks: 8 warps x 2 rows
}

// round 15
// speedup vs baseline: 1.0901x; 1.0901x over previous
#include <cuda_runtime.h>

#define D_MODEL 4096
#define D_INNER 8192
#define D_STATE 16
#define DT_RANK 8
#define XP_DIM  (DT_RANK + 2 * D_STATE)   // 40

// ---------------- scratch (device globals; no allocation allowed) ------------
__device__ float g_x_conv[D_INNER];
__device__ float g_z[D_INNER];
__device__ float g_xp[XP_DIM];
__device__ float g_y[D_INNER];
__device__ float g_h_scratch[D_INNER * D_STATE];

// ---------------- helpers ----------------------------------------------------
__device__ __forceinline__ float warp_reduce(float v) {
#pragma unroll
    for (int o = 16; o; o >>= 1) v += __shfl_xor_sync(0xffffffffu, v, o);
    return v;
}

__device__ __forceinline__ float fma4(float4 w, float4 v, float a) {
    return fmaf(w.x, v.x, fmaf(w.y, v.y, fmaf(w.z, v.z, fmaf(w.w, v.w, a))));
}

__device__ __forceinline__ float sigmoidf_(float v) { return 1.f / (1.f + expf(-v)); }

// 8 KB chunk dot-product: 512 float4, lane-strided, 4 independent chains.
__device__ __forceinline__ float dot_chunk_8kb(
    const float4* __restrict__ Wr, const float4* __restrict__ vv, int lane)
{
    float a0 = 0.f, a1 = 0.f, a2 = 0.f, a3 = 0.f;
#pragma unroll
    for (int k = 0; k < 16; k += 4) {          // 512 float4 / 32 lanes = 16/lane
        const int b = k * 32 + lane;
        const float4 v0 = __ldg(&vv[b]);
        const float4 v1 = __ldg(&vv[b + 32]);
        const float4 v2 = __ldg(&vv[b + 64]);
        const float4 v3 = __ldg(&vv[b + 96]);
        const float4 w0 = Wr[b],      w1 = Wr[b + 32],
                     w2 = Wr[b + 64], w3 = Wr[b + 96];
        a0 = fma4(w0, v0, a0);  a1 = fma4(w1, v1, a1);
        a2 = fma4(w2, v2, a2);  a3 = fma4(w3, v3, a3);
    }
    return warp_reduce((a0 + a1) + (a2 + a3));
}

// ---------------- kernel 1: xz = W_in @ x, fused conv+silu epilogue ----------
// Split-K x2: each warp streams a HALF row (2048 floats = 8KB).
// Block = 8 warps = 2 channels x {x-row, z-row} x 2 halves. Grid = 4096.
__global__ void __launch_bounds__(256) k_gemv_in(
    const float* __restrict__ W,        // (16384, 4096)
    const float* __restrict__ x,        // (4096,)
    const float* __restrict__ cb,       // conv_buffer (8192, 3)
    const float* __restrict__ cw,       // conv_w (8192, 4)
    const float* __restrict__ conv_b)   // (8192,)
{
    const int warp = threadIdx.x >> 5, lane = threadIdx.x & 31;
    const int row_idx = warp >> 1;                 // 0..3: (c0,x)(c0,z)(c1,x)(c1,z)
    const int half    = warp & 1;                  // which 2048-float half
    const int ch      = blockIdx.x * 2 + (row_idx >> 1);
    const int is_z    = row_idx & 1;
    const int row     = ch + is_z * D_INNER;

    const float4* __restrict__ Wr =
        (const float4*)(W + (size_t)row * D_MODEL) + half * 512;
    const float4* __restrict__ xv = (const float4*)x + half * 512;

    const float part = dot_chunk_8kb(Wr, xv, lane);

    __shared__ float s[8];
    if (lane == 0) s[warp] = part;
    __syncthreads();

    if (threadIdx.x < 2) {
        const int t = threadIdx.x;
        const int c = blockIdx.x * 2 + t;
        const float accx = s[4 * t] + s[4 * t + 1];
        const float accz = s[4 * t + 2] + s[4 * t + 3];
        // conv_in = [cb[:,1], cb[:,2], v, v] ; weights [w0,w1,w2,w3]
        const float c1 = cb[c * 3 + 1];
        const float c2 = cb[c * 3 + 2];
        const float4 w4 = *(const float4*)(cw + c * 4);
        const float sv = fmaf(c1, w4.x, fmaf(c2, w4.y, fmaf(accx, w4.z + w4.w, conv_b[c])));
        g_x_conv[c] = sv * sigmoidf_(sv);   // silu
        g_z[c] = accz;
    }
}

// ---------------- kernel 2: xp = W_xp @ x_conv  (40 x 8192) ------------------
__global__ void __launch_bounds__(256) k_xp(const float* __restrict__ Wxp)
{
    const int row = blockIdx.x;                     // 0..39
    const float4* __restrict__ Wr = (const float4*)(Wxp + (size_t)row * D_INNER);
    const float4* __restrict__ xc = (const float4*)g_x_conv;

    float acc = 0.f;
    for (int idx = threadIdx.x; idx < D_INNER / 4; idx += 256) {
        acc = fma4(Wr[idx], xc[idx], acc);
    }
    __shared__ float sred[8];
    acc = warp_reduce(acc);
    if ((threadIdx.x & 31) == 0) sred[threadIdx.x >> 5] = acc;
    __syncthreads();
    if (threadIdx.x < 32) {
        float v = (threadIdx.x < 8) ? sred[threadIdx.x] : 0.f;
        v = warp_reduce(v);
        if (threadIdx.x == 0) g_xp[row] = v;
    }
}

// ---------------- kernel 3: dt/softplus + SSM state update + gate ------------
// One thread per channel (8192). Writes new_h and g_y.
__global__ void __launch_bounds__(256) k_state(
    const float* __restrict__ Wdt,      // (8192, 8)
    const float* __restrict__ bdt,      // (8192,)
    const float* __restrict__ Alog,     // (8192, 16)
    const float* __restrict__ h,        // ssm_state (8192, 16)
    const float* __restrict__ Dp,       // (8192,)
    float* __restrict__ newh)           // (8192, 16) or nullptr
{
    const int i = blockIdx.x * 256 + threadIdx.x;

    __shared__ float sxp[XP_DIM];
    if (threadIdx.x < XP_DIM) sxp[threadIdx.x] = g_xp[threadIdx.x];
    __syncthreads();

    // dt = softplus(W_dt[i,:] . xp[:8] + b_dt[i])
    const float4* wd = (const float4*)(Wdt + (size_t)i * DT_RANK);
    const float4 w0 = wd[0], w1 = wd[1];
    float dtin = bdt[i];
    dtin += w0.x * sxp[0] + w0.y * sxp[1] + w0.z * sxp[2] + w0.w * sxp[3]
          + w1.x * sxp[4] + w1.y * sxp[5] + w1.z * sxp[6] + w1.w * sxp[7];
    const float dt = (dtin > 20.f) ? dtin : log1pf(expf(dtin));

    const float xc = g_x_conv[i];
    const float* Ar = Alog + (size_t)i * D_STATE;
    const float* hr = h    + (size_t)i * D_STATE;
    float* nr = (newh ? newh : g_h_scratch) + (size_t)i * D_STATE;

    float acc = 0.f;
#pragma unroll
    for (int s = 0; s < D_STATE; s++) {
        const float abar = expf(-dt * expf(Ar[s]));               // exp(dt * -exp(A_log))
        const float nh = fmaf(abar, hr[s], dt * sxp[DT_RANK + s] * xc);
        nr[s] = nh;
        acc = fmaf(nh, sxp[DT_RANK + D_STATE + s], acc);
    }
    const float y = acc + Dp[i] * xc;
    const float z = g_z[i];
    g_y[i] = y * (z * sigmoidf_(z));
}

// ---------------- kernel 4: out = W_out @ y  (4096 x 8192) -------------------
// Split-K x4: each warp streams a QUARTER row (2048 floats = 8KB).
// Block = 8 warps = 2 rows x 4 quarters. Grid = 2048.
__global__ void __launch_bounds__(256) k_gemv_out(
    const float* __restrict__ W, float* __restrict__ out)
{
    const int warp = threadIdx.x >> 5, lane = threadIdx.x & 31;
    const int row_idx = warp >> 2;                 // 0..1
    const int q       = warp & 3;                  // quarter 0..3
    const int r       = blockIdx.x * 2 + row_idx;  // 0..4095

    const float4* __restrict__ Wr =
        (const float4*)(W + (size_t)r * D_INNER) + q * 512;
    const float4* __restrict__ yv = (const float4*)g_y + q * 512;

    const float part = dot_chunk_8kb(Wr, yv, lane);

    __shared__ float s[8];
    if (lane == 0) s[warp] = part;
    __syncthreads();

    if (threadIdx.x < 2) {
        const int t = threadIdx.x;
        out[blockIdx.x * 2 + t] = s[4 * t] + s[4 * t + 1] + s[4 * t + 2] + s[4 * t + 3];
    }
}

// ---------------- launch ------------------------------------------------------
extern "C" void kernel_launch(void* const* d_in, const int* in_sizes, int n_in,
                              void* d_out, int out_size)
{
    const float* x       = (const float*)d_in[0];
    const float* h       = (const float*)d_in[1];   // ssm_state
    const float* cb      = (const float*)d_in[2];   // conv_buffer
    const float* W_in    = (const float*)d_in[3];
    const float* conv_w  = (const float*)d_in[4];
    const float* conv_b  = (const float*)d_in[5];
    const float* W_xp    = (const float*)d_in[6];
    const float* W_dt    = (const float*)d_in[7];
    const float* b_dt    = (const float*)d_in[8];
    const float* A_log   = (const float*)d_in[9];
    const float* D_param = (const float*)d_in[10];
    const float* W_out   = (const float*)d_in[11];

    float* out = (float*)d_out;
    // tuple output (out, new_h) concatenated: [4096][8192*16]
    float* newh = (out_size >= D_MODEL + D_INNER * D_STATE) ? (out + D_MODEL) : nullptr;

    k_gemv_in <<<D_INNER / 2, 256>>>(W_in, x, cb, conv_w, conv_b);   // 4096 blocks
    k_xp      <<<XP_DIM, 256>>>(W_xp);
    k_state   <<<D_INNER / 256, 256>>>(W_dt, b_dt, A_log, h, D_param, newh);
    k_gemv_out<<<D_MODEL / 2, 256>>>(W_out, out);                    // 2048 blocks
}